// round 1
// baseline (speedup 1.0000x reference)
#include <cuda_runtime.h>
#include <math.h>

#define BATCH 4096
#define D1 200
#define W_IN 400
#define FW 9
#define OC 32
#define W_OUT 392
#define FC_LEN 12544
#define FC1_LEN 288
#define EPSBN 1e-5f

// ---------------- scratch (device globals; no allocation allowed) ------------
__device__ float g_flat[BATCH * FC_LEN];      // [4096, 12544]  ~205 MB
__device__ float g_ks[BATCH * FC1_LEN];       // per-example filters * inv1
__device__ float g_h[BATCH * W_IN];           // post-fc, post-bn2
__device__ float g_scale1[FC1_LEN];
__device__ float g_shift1[FC1_LEN];
__device__ float g_scale2[W_IN];
__device__ float g_shift2[W_IN];
__device__ float g_c1[OC];
__device__ float g_x0[2];                     // bn0 folded scale/offset

// ---------------- setup: fold all batchnorms into scale/shift ----------------
__global__ void setup_kernel(
    const float* __restrict__ bn0_g, const float* __restrict__ bn0_b,
    const float* __restrict__ bn0_m, const float* __restrict__ bn0_v,
    const float* __restrict__ fc1_b,
    const float* __restrict__ bn1_g, const float* __restrict__ bn1_b,
    const float* __restrict__ bn1_m, const float* __restrict__ bn1_v,
    const float* __restrict__ fc_b,
    const float* __restrict__ bn2_g, const float* __restrict__ bn2_b,
    const float* __restrict__ bn2_m, const float* __restrict__ bn2_v)
{
    int t = threadIdx.x;
    if (t < FC1_LEN) {
        int o = t / FW;
        float inv1 = bn1_g[o] * rsqrtf(bn1_v[o] + EPSBN);
        g_scale1[t] = inv1;
        g_shift1[t] = fc1_b[t] * inv1;
    }
    if (t < W_IN) {
        float s2 = bn2_g[t] * rsqrtf(bn2_v[t] + EPSBN);
        g_scale2[t] = s2;
        g_shift2[t] = (fc_b[t] - bn2_m[t]) * s2 + bn2_b[t];
    }
    if (t < OC) {
        float inv1 = bn1_g[t] * rsqrtf(bn1_v[t] + EPSBN);
        g_c1[t] = bn1_b[t] - bn1_m[t] * inv1;
    }
    if (t == 0) {
        float s0 = bn0_g[0] * rsqrtf(bn0_v[0] + EPSBN);
        g_x0[0] = s0;
        g_x0[1] = bn0_b[0] - bn0_m[0] * s0;
    }
}

// ---------------- generic tiled NT SGEMM:  C = gather(A) * B^T ---------------
// A: [M,K] row-major (optionally row-gathered), B: [N,K] row-major.
// Epilogue: C[m,n] = acc*scale[n] + shift[n].  BM=BN=64, BK=16, 128 threads.
__device__ __forceinline__ float4 ld4p(const float* p, bool v)
{
    if (v) return *(const float4*)p;
    return make_float4(0.f, 0.f, 0.f, 0.f);
}

template <bool GATHER>
__global__ __launch_bounds__(128) void gemm_nt_kernel(
    const float* __restrict__ A, const int* __restrict__ ridx,
    const float* __restrict__ B, float* __restrict__ C,
    int N, int K,
    const float* __restrict__ scale, const float* __restrict__ shift)
{
    __shared__ float As[16][68];
    __shared__ float Bs[16][68];

    const int tid = threadIdx.x;
    const int m0 = blockIdx.x * 64;
    const int n0 = blockIdx.y * 64;

    const int ldRow = tid >> 2;        // 0..31
    const int ldK   = (tid & 3) << 2;  // 0,4,8,12

    const int ar0 = m0 + ldRow, ar1 = ar0 + 32;
    const float* ap0 = A + (size_t)(GATHER ? ridx[ar0] : ar0) * K;
    const float* ap1 = A + (size_t)(GATHER ? ridx[ar1] : ar1) * K;

    const int br0 = n0 + ldRow, br1 = br0 + 32;
    const bool bv0 = br0 < N, bv1 = br1 < N;
    const float* bp0 = B + (size_t)(bv0 ? br0 : 0) * K;
    const float* bp1 = B + (size_t)(bv1 ? br1 : 0) * K;

    const int tmi = (tid & 7) << 3;    // row offset 0..56
    const int tni = (tid >> 3) << 2;   // col offset 0..60

    float acc[8][4];
#pragma unroll
    for (int i = 0; i < 8; i++)
#pragma unroll
        for (int j = 0; j < 4; j++) acc[i][j] = 0.f;

    const int nk = (K + 15) >> 4;

    float4 ra0, ra1, rb0, rb1;
    {
        int kk = ldK;
        bool kv = kk < K;
        ra0 = ld4p(ap0 + kk, kv);
        ra1 = ld4p(ap1 + kk, kv);
        rb0 = ld4p(bp0 + kk, kv && bv0);
        rb1 = ld4p(bp1 + kk, kv && bv1);
    }

    for (int kt = 0; kt < nk; kt++) {
        As[ldK + 0][ldRow] = ra0.x; As[ldK + 1][ldRow] = ra0.y;
        As[ldK + 2][ldRow] = ra0.z; As[ldK + 3][ldRow] = ra0.w;
        As[ldK + 0][ldRow + 32] = ra1.x; As[ldK + 1][ldRow + 32] = ra1.y;
        As[ldK + 2][ldRow + 32] = ra1.z; As[ldK + 3][ldRow + 32] = ra1.w;
        Bs[ldK + 0][ldRow] = rb0.x; Bs[ldK + 1][ldRow] = rb0.y;
        Bs[ldK + 2][ldRow] = rb0.z; Bs[ldK + 3][ldRow] = rb0.w;
        Bs[ldK + 0][ldRow + 32] = rb1.x; Bs[ldK + 1][ldRow + 32] = rb1.y;
        Bs[ldK + 2][ldRow + 32] = rb1.z; Bs[ldK + 3][ldRow + 32] = rb1.w;
        __syncthreads();

        if (kt + 1 < nk) {
            int kk = ((kt + 1) << 4) + ldK;
            bool kv = kk < K;
            ra0 = ld4p(ap0 + kk, kv);
            ra1 = ld4p(ap1 + kk, kv);
            rb0 = ld4p(bp0 + kk, kv && bv0);
            rb1 = ld4p(bp1 + kk, kv && bv1);
        }

#pragma unroll
        for (int k = 0; k < 16; k++) {
            float4 a0 = *(const float4*)&As[k][tmi];
            float4 a1 = *(const float4*)&As[k][tmi + 4];
            float4 bb = *(const float4*)&Bs[k][tni];
            float av[8] = {a0.x, a0.y, a0.z, a0.w, a1.x, a1.y, a1.z, a1.w};
            float bv[4] = {bb.x, bb.y, bb.z, bb.w};
#pragma unroll
            for (int i = 0; i < 8; i++)
#pragma unroll
                for (int j = 0; j < 4; j++)
                    acc[i][j] += av[i] * bv[j];
        }
        __syncthreads();
    }

#pragma unroll
    for (int j = 0; j < 4; j++) {
        int col = n0 + tni + j;
        if (col < N) {
            float sc = scale[col], sh = shift[col];
#pragma unroll
            for (int i = 0; i < 8; i++) {
                int row = m0 + tmi + i;
                C[(size_t)row * N + col] = acc[i][j] * sc + sh;
            }
        }
    }
}

// ---------------- per-example conv: flat = bn1(conv(bn0(x), k)) --------------
// One CTA per example, 256 threads = 8 warps; warp w handles OC rows 4w..4w+3,
// lanes sweep W_OUT (coalesced stores of g_flat).
__global__ __launch_bounds__(256) void conv_kernel(
    const int* __restrict__ e1_idx, const int* __restrict__ e2_idx,
    const float* __restrict__ E_table)
{
    __shared__ float sx[W_IN];
    __shared__ float sks[FC1_LEN];
    __shared__ float sc1[OC];

    const int b = blockIdx.x;
    const int tid = threadIdx.x;
    const float s0 = g_x0[0], o0 = g_x0[1];
    const int e1 = e1_idx[b], e2 = e2_idx[b];

    for (int t = tid; t < W_IN; t += 256) {
        float e = (t < D1) ? E_table[(size_t)e1 * D1 + t]
                           : E_table[(size_t)e2 * D1 + (t - D1)];
        sx[t] = e * s0 + o0;
    }
    for (int t = tid; t < FC1_LEN; t += 256) sks[t] = g_ks[(size_t)b * FC1_LEN + t];
    if (tid < OC) sc1[tid] = g_c1[tid];
    __syncthreads();

    const int warp = tid >> 5, lane = tid & 31;
#pragma unroll
    for (int oi = 0; oi < 4; oi++) {
        const int o = warp * 4 + oi;
        float kf[FW];
#pragma unroll
        for (int j = 0; j < FW; j++) kf[j] = sks[o * FW + j];
        const float c = sc1[o];
        float* dst = g_flat + (size_t)b * FC_LEN + o * W_OUT;
#pragma unroll
        for (int it = 0; it < 13; it++) {
            int w = it * 32 + lane;
            if (w < W_OUT) {
                float acc = c;
#pragma unroll
                for (int j = 0; j < FW; j++) acc += sx[w + j] * kf[j];
                dst[w] = acc;
            }
        }
    }
}

// ---------------- final: out[b] = tanh(dot(h[b], fc2_w) + fc2_b) + bias ------
__global__ __launch_bounds__(256) void final_kernel(
    const float* __restrict__ fc2_w, const float* __restrict__ fc2_b,
    const float* __restrict__ bias, float* __restrict__ out)
{
    const int gw = (blockIdx.x * blockDim.x + threadIdx.x) >> 5;
    const int lane = threadIdx.x & 31;
    if (gw >= BATCH) return;
    const float* hrow = g_h + (size_t)gw * W_IN;
    float acc = 0.f;
    for (int t = lane; t < W_IN; t += 32) acc += hrow[t] * fc2_w[t];
#pragma unroll
    for (int s = 16; s > 0; s >>= 1) acc += __shfl_xor_sync(0xffffffffu, acc, s);
    if (lane == 0) out[gw] = tanhf(acc + fc2_b[0]) + bias[0];
}

// -----------------------------------------------------------------------------
extern "C" void kernel_launch(void* const* d_in, const int* in_sizes, int n_in,
                              void* d_out, int out_size)
{
    const int*   e1_idx  = (const int*)d_in[0];
    const int*   r_idx   = (const int*)d_in[1];
    const int*   e2_idx  = (const int*)d_in[2];
    const float* E_table = (const float*)d_in[3];
    const float* R_table = (const float*)d_in[4];
    const float* bn0_g   = (const float*)d_in[5];
    const float* bn0_b   = (const float*)d_in[6];
    const float* bn0_m   = (const float*)d_in[7];
    const float* bn0_v   = (const float*)d_in[8];
    const float* fc1_w   = (const float*)d_in[9];
    const float* fc1_b   = (const float*)d_in[10];
    const float* bn1_g   = (const float*)d_in[11];
    const float* bn1_b   = (const float*)d_in[12];
    const float* bn1_m   = (const float*)d_in[13];
    const float* bn1_v   = (const float*)d_in[14];
    const float* fc_w    = (const float*)d_in[15];
    const float* fc_b    = (const float*)d_in[16];
    const float* bn2_g   = (const float*)d_in[17];
    const float* bn2_b   = (const float*)d_in[18];
    const float* bn2_m   = (const float*)d_in[19];
    const float* bn2_v   = (const float*)d_in[20];
    const float* fc2_w   = (const float*)d_in[21];
    const float* fc2_b   = (const float*)d_in[22];
    const float* bias    = (const float*)d_in[23];

    float *p_ks, *p_flat, *p_h, *p_s1, *p_sh1, *p_s2, *p_sh2;
    cudaGetSymbolAddress((void**)&p_ks,   g_ks);
    cudaGetSymbolAddress((void**)&p_flat, g_flat);
    cudaGetSymbolAddress((void**)&p_h,    g_h);
    cudaGetSymbolAddress((void**)&p_s1,   g_scale1);
    cudaGetSymbolAddress((void**)&p_sh1,  g_shift1);
    cudaGetSymbolAddress((void**)&p_s2,   g_scale2);
    cudaGetSymbolAddress((void**)&p_sh2,  g_shift2);

    setup_kernel<<<1, 512>>>(bn0_g, bn0_b, bn0_m, bn0_v, fc1_b,
                             bn1_g, bn1_b, bn1_m, bn1_v,
                             fc_b, bn2_g, bn2_b, bn2_m, bn2_v);

    // GEMM1: ks[4096,288] = gather(R_table, r_idx) @ fc1_w^T, *inv1 epilogue
    gemm_nt_kernel<true><<<dim3(BATCH / 64, (FC1_LEN + 63) / 64), 128>>>(
        R_table, r_idx, fc1_w, p_ks, FC1_LEN, D1, p_s1, p_sh1);

    // conv: flat[4096,12544]
    conv_kernel<<<BATCH, 256>>>(e1_idx, e2_idx, E_table);

    // GEMM2: h[4096,400] = flat @ fc_w^T, bn2 epilogue
    gemm_nt_kernel<false><<<dim3(BATCH / 64, (W_IN + 63) / 64), 128>>>(
        p_flat, nullptr, fc_w, p_h, W_IN, FC_LEN, p_s2, p_sh2);

    // final tanh head
    final_kernel<<<(BATCH * 32 + 255) / 256, 256>>>(fc2_w, fc2_b, bias, (float*)d_out);
}

// round 4
// speedup vs baseline: 2.3918x; 2.3918x over previous
#include <cuda_runtime.h>
#include <cuda_bf16.h>
#include <cstdint>
#include <math.h>

#define BATCH 4096
#define D1 200
#define W_IN 400
#define FW 9
#define OC 32
#define W_OUT 392
#define FC_LEN 12544
#define FC1_LEN 288
#define EPSBN 1e-5f

// GEMM2 tiling
#define BM 128
#define BN 80
#define BK 32
#define NKT (FC_LEN / BK)      // 392
#define ROWB 80                 // smem row stride in bytes (32 bf16 + 16B pad)
#define OFF_AL 10240            // 128*80
#define OFF_BH 20480
#define OFF_BL 26880            // +80*80
#define PBUF 33280
#define SMEM2 (2 * PBUF)        // 66560

// ---------------- device-global scratch (no allocation allowed) --------------
__device__ __align__(16) __nv_bfloat16 g_ah[(size_t)BATCH * FC_LEN];
__device__ __align__(16) __nv_bfloat16 g_al[(size_t)BATCH * FC_LEN];
__device__ __align__(16) __nv_bfloat16 g_bh[(size_t)W_IN * FC_LEN];
__device__ __align__(16) __nv_bfloat16 g_bl[(size_t)W_IN * FC_LEN];
__device__ float g_h[(size_t)BATCH * W_IN];
__device__ float g_ks[BATCH * FC1_LEN];
__device__ float g_scale1[FC1_LEN];
__device__ float g_shift1[FC1_LEN];
__device__ float g_scale2[W_IN];
__device__ float g_shift2[W_IN];
__device__ float g_c1[OC];
__device__ float g_x0[2];

// ---------------- PTX helpers ------------------------------------------------
__device__ __forceinline__ uint32_t smem_u32(const void* p) {
    uint32_t a;
    asm("{ .reg .u64 t; cvta.to.shared.u64 t, %1; cvt.u32.u64 %0, t; }"
        : "=r"(a) : "l"(p));
    return a;
}
__device__ __forceinline__ void cp16(uint32_t sa, const void* ga) {
    asm volatile("cp.async.cg.shared.global [%0], [%1], 16;" :: "r"(sa), "l"(ga));
}
#define CP_COMMIT() asm volatile("cp.async.commit_group;" ::: "memory")
#define CP_WAIT1()  asm volatile("cp.async.wait_group 1;" ::: "memory")
#define CP_WAIT0()  asm volatile("cp.async.wait_group 0;" ::: "memory")

#define LDSM4(r, addr) \
    asm volatile("ldmatrix.sync.aligned.m8n8.x4.shared.b16 {%0,%1,%2,%3}, [%4];" \
                 : "=r"((r)[0]), "=r"((r)[1]), "=r"((r)[2]), "=r"((r)[3]) : "r"(addr))
#define LDSM2(r, addr) \
    asm volatile("ldmatrix.sync.aligned.m8n8.x2.shared.b16 {%0,%1}, [%2];" \
                 : "=r"((r)[0]), "=r"((r)[1]) : "r"(addr))

#define MMA_BF16(c, a, b) \
    asm volatile("mma.sync.aligned.m16n8k16.row.col.f32.bf16.bf16.f32 " \
                 "{%0,%1,%2,%3},{%4,%5,%6,%7},{%8,%9},{%0,%1,%2,%3};" \
                 : "+f"((c)[0]), "+f"((c)[1]), "+f"((c)[2]), "+f"((c)[3]) \
                 : "r"((a)[0]), "r"((a)[1]), "r"((a)[2]), "r"((a)[3]), \
                   "r"((b)[0]), "r"((b)[1]))

// ---------------- setup: fold batchnorms ------------------------------------
__global__ void setup_kernel(
    const float* __restrict__ bn0_g, const float* __restrict__ bn0_b,
    const float* __restrict__ bn0_m, const float* __restrict__ bn0_v,
    const float* __restrict__ fc1_b,
    const float* __restrict__ bn1_g, const float* __restrict__ bn1_b,
    const float* __restrict__ bn1_m, const float* __restrict__ bn1_v,
    const float* __restrict__ fc_b,
    const float* __restrict__ bn2_g, const float* __restrict__ bn2_b,
    const float* __restrict__ bn2_m, const float* __restrict__ bn2_v)
{
    int t = threadIdx.x;
    if (t < FC1_LEN) {
        int o = t / FW;
        float inv1 = bn1_g[o] * rsqrtf(bn1_v[o] + EPSBN);
        g_scale1[t] = inv1;
        g_shift1[t] = fc1_b[t] * inv1;
    }
    if (t < W_IN) {
        float s2 = bn2_g[t] * rsqrtf(bn2_v[t] + EPSBN);
        g_scale2[t] = s2;
        g_shift2[t] = (fc_b[t] - bn2_m[t]) * s2 + bn2_b[t];
    }
    if (t < OC) {
        float inv1 = bn1_g[t] * rsqrtf(bn1_v[t] + EPSBN);
        g_c1[t] = bn1_b[t] - bn1_m[t] * inv1;
    }
    if (t == 0) {
        float s0 = bn0_g[0] * rsqrtf(bn0_v[0] + EPSBN);
        g_x0[0] = s0;
        g_x0[1] = bn0_b[0] - bn0_m[0] * s0;
    }
}

// ---------------- split fc_w into bf16 hi/lo --------------------------------
__global__ __launch_bounds__(256) void splitw_kernel(const float* __restrict__ w)
{
    int i = blockIdx.x * 256 + threadIdx.x;
#pragma unroll
    for (int u = 0; u < 4; u++) {
        size_t idx = (size_t)i + (size_t)u * 1254400;
        float v = w[idx];
        __nv_bfloat16 h = __float2bfloat16(v);
        g_bh[idx] = h;
        g_bl[idx] = __float2bfloat16(v - __bfloat162float(h));
    }
}

// ---------------- GEMM1 (fp32, small): ks = gather(R) @ fc1_w^T --------------
__device__ __forceinline__ float4 ld4p(const float* p, bool v)
{
    if (v) return *(const float4*)p;
    return make_float4(0.f, 0.f, 0.f, 0.f);
}

__global__ __launch_bounds__(128) void gemm1_kernel(
    const float* __restrict__ A, const int* __restrict__ ridx,
    const float* __restrict__ B, int N, int K)
{
    __shared__ float As[16][68];
    __shared__ float Bs[16][68];

    const int tid = threadIdx.x;
    const int m0 = blockIdx.x * 64;
    const int n0 = blockIdx.y * 64;
    const int ldRow = tid >> 2;
    const int ldK = (tid & 3) << 2;

    const int ar0 = m0 + ldRow, ar1 = ar0 + 32;
    const float* ap0 = A + (size_t)ridx[ar0] * K;
    const float* ap1 = A + (size_t)ridx[ar1] * K;
    const int br0 = n0 + ldRow, br1 = br0 + 32;
    const bool bv0 = br0 < N, bv1 = br1 < N;
    const float* bp0 = B + (size_t)(bv0 ? br0 : 0) * K;
    const float* bp1 = B + (size_t)(bv1 ? br1 : 0) * K;

    const int tmi = (tid & 7) << 3;
    const int tni = (tid >> 3) << 2;

    float acc[8][4];
#pragma unroll
    for (int i = 0; i < 8; i++)
#pragma unroll
        for (int j = 0; j < 4; j++) acc[i][j] = 0.f;

    const int nk = (K + 15) >> 4;
    float4 ra0, ra1, rb0, rb1;
    {
        bool kv = ldK < K;
        ra0 = ld4p(ap0 + ldK, kv); ra1 = ld4p(ap1 + ldK, kv);
        rb0 = ld4p(bp0 + ldK, kv && bv0); rb1 = ld4p(bp1 + ldK, kv && bv1);
    }
    for (int kt = 0; kt < nk; kt++) {
        As[ldK + 0][ldRow] = ra0.x; As[ldK + 1][ldRow] = ra0.y;
        As[ldK + 2][ldRow] = ra0.z; As[ldK + 3][ldRow] = ra0.w;
        As[ldK + 0][ldRow + 32] = ra1.x; As[ldK + 1][ldRow + 32] = ra1.y;
        As[ldK + 2][ldRow + 32] = ra1.z; As[ldK + 3][ldRow + 32] = ra1.w;
        Bs[ldK + 0][ldRow] = rb0.x; Bs[ldK + 1][ldRow] = rb0.y;
        Bs[ldK + 2][ldRow] = rb0.z; Bs[ldK + 3][ldRow] = rb0.w;
        Bs[ldK + 0][ldRow + 32] = rb1.x; Bs[ldK + 1][ldRow + 32] = rb1.y;
        Bs[ldK + 2][ldRow + 32] = rb1.z; Bs[ldK + 3][ldRow + 32] = rb1.w;
        __syncthreads();
        if (kt + 1 < nk) {
            int kk = ((kt + 1) << 4) + ldK;
            bool kv = kk < K;
            ra0 = ld4p(ap0 + kk, kv); ra1 = ld4p(ap1 + kk, kv);
            rb0 = ld4p(bp0 + kk, kv && bv0); rb1 = ld4p(bp1 + kk, kv && bv1);
        }
#pragma unroll
        for (int k = 0; k < 16; k++) {
            float4 a0 = *(const float4*)&As[k][tmi];
            float4 a1 = *(const float4*)&As[k][tmi + 4];
            float4 bb = *(const float4*)&Bs[k][tni];
            float av[8] = {a0.x, a0.y, a0.z, a0.w, a1.x, a1.y, a1.z, a1.w};
            float bv[4] = {bb.x, bb.y, bb.z, bb.w};
#pragma unroll
            for (int i = 0; i < 8; i++)
#pragma unroll
                for (int j = 0; j < 4; j++) acc[i][j] += av[i] * bv[j];
        }
        __syncthreads();
    }
#pragma unroll
    for (int j = 0; j < 4; j++) {
        int col = n0 + tni + j;
        if (col < N) {
            float sc = g_scale1[col], sh = g_shift1[col];
#pragma unroll
            for (int i = 0; i < 8; i++)
                g_ks[(size_t)(m0 + tmi + i) * N + col] = acc[i][j] * sc + sh;
        }
    }
}

// ---------------- conv: emits bf16 hi/lo of bn1(conv(bn0(x), k)) -------------
__global__ __launch_bounds__(256) void conv_kernel(
    const int* __restrict__ e1_idx, const int* __restrict__ e2_idx,
    const float* __restrict__ E_table)
{
    __shared__ float sx[W_IN];
    __shared__ float sks[FC1_LEN];
    __shared__ float sc1[OC];

    const int b = blockIdx.x;
    const int tid = threadIdx.x;
    const float s0 = g_x0[0], o0 = g_x0[1];
    const int e1 = e1_idx[b], e2 = e2_idx[b];

    for (int t = tid; t < W_IN; t += 256) {
        float e = (t < D1) ? E_table[(size_t)e1 * D1 + t]
                           : E_table[(size_t)e2 * D1 + (t - D1)];
        sx[t] = e * s0 + o0;
    }
    for (int t = tid; t < FC1_LEN; t += 256) sks[t] = g_ks[(size_t)b * FC1_LEN + t];
    if (tid < OC) sc1[tid] = g_c1[tid];
    __syncthreads();

    const int warp = tid >> 5, lane = tid & 31;
#pragma unroll
    for (int oi = 0; oi < 4; oi++) {
        const int o = warp * 4 + oi;
        float kf[FW];
#pragma unroll
        for (int j = 0; j < FW; j++) kf[j] = sks[o * FW + j];
        const float c = sc1[o];
        size_t base = (size_t)b * FC_LEN + o * W_OUT;
#pragma unroll
        for (int it = 0; it < 13; it++) {
            int w = it * 32 + lane;
            if (w < W_OUT) {
                float acc = c;
#pragma unroll
                for (int j = 0; j < FW; j++) acc += sx[w + j] * kf[j];
                __nv_bfloat16 h = __float2bfloat16(acc);
                g_ah[base + w] = h;
                g_al[base + w] = __float2bfloat16(acc - __bfloat162float(h));
            }
        }
    }
}

// ---------------- GEMM2: mma.sync bf16 3-term split --------------------------
// grid (32, 5), 128 threads (4 warps: warpM=wid/2, warpN=wid%2).
// CTA tile 128x80, warp tile 64x40 (4x5 m16n8 tiles), BK=32, cp.async 2-stage.
__global__ __launch_bounds__(128, 2) void gemm2_kernel()
{
    extern __shared__ char smem[];
    const int tid = threadIdx.x;
    const int wid = tid >> 5, lane = tid & 31;
    const int warpM = wid >> 1, warpN = wid & 1;
    const int m0 = blockIdx.x * BM;
    const int n0 = blockIdx.y * BN;
    const uint32_t sb = smem_u32(smem);

    float acc[4][5][4];
#pragma unroll
    for (int mi = 0; mi < 4; mi++)
#pragma unroll
        for (int nj = 0; nj < 5; nj++)
#pragma unroll
            for (int q = 0; q < 4; q++) acc[mi][nj][q] = 0.f;

    // cp.async tile loader
    auto issue = [&](int kt, int buf) {
        const int kb = kt * BK;
        const uint32_t s = sb + buf * PBUF;
#pragma unroll
        for (int i = 0; i < 4; i++) {
            int idx = tid + i * 128;          // 0..511
            int r = idx >> 2, c = idx & 3;
            size_t go = (size_t)(m0 + r) * FC_LEN + kb + c * 8;
            uint32_t so = r * ROWB + c * 16;
            cp16(s + so, g_ah + go);
            cp16(s + OFF_AL + so, g_al + go);
        }
#pragma unroll
        for (int i = 0; i < 3; i++) {
            int idx = tid + i * 128;          // 0..383, need <320
            if (idx < 320) {
                int r = idx >> 2, c = idx & 3;
                size_t go = (size_t)(n0 + r) * FC_LEN + kb + c * 8;
                uint32_t so = r * ROWB + c * 16;
                cp16(s + OFF_BH + so, g_bh + go);
                cp16(s + OFF_BL + so, g_bl + go);
            }
        }
        CP_COMMIT();
    };

    issue(0, 0);

    const uint32_t aRow = (lane & 15), aCB = (lane >> 4) << 4;
    const int l16 = lane & 15;
    const uint32_t bRow = l16 & 7, bCB = (l16 >> 3) << 4;
    const uint32_t aOff = (warpM * 64 + aRow) * ROWB + aCB;
    const uint32_t bOff = (warpN * 40 + bRow) * ROWB + bCB;

    for (int kt = 0; kt < NKT; kt++) {
        const int buf = kt & 1;
        if (kt + 1 < NKT) { issue(kt + 1, buf ^ 1); CP_WAIT1(); }
        else             { CP_WAIT0(); }
        __syncthreads();

        const uint32_t sA = sb + buf * PBUF;
#pragma unroll
        for (int kk = 0; kk < 2; kk++) {
            const uint32_t koff = kk * 32;
            uint32_t ah[4][4], al[4][4], bh[5][2], bl[5][2];
#pragma unroll
            for (int mi = 0; mi < 4; mi++)
                LDSM4(ah[mi], sA + aOff + mi * 16 * ROWB + koff);
#pragma unroll
            for (int mi = 0; mi < 4; mi++)
                LDSM4(al[mi], sA + OFF_AL + aOff + mi * 16 * ROWB + koff);
#pragma unroll
            for (int nj = 0; nj < 5; nj++)
                LDSM2(bh[nj], sA + OFF_BH + bOff + nj * 8 * ROWB + koff);
#pragma unroll
            for (int nj = 0; nj < 5; nj++)
                LDSM2(bl[nj], sA + OFF_BL + bOff + nj * 8 * ROWB + koff);

#pragma unroll
            for (int mi = 0; mi < 4; mi++)
#pragma unroll
                for (int nj = 0; nj < 5; nj++) {
                    MMA_BF16(acc[mi][nj], ah[mi], bh[nj]);
                    MMA_BF16(acc[mi][nj], al[mi], bh[nj]);
                    MMA_BF16(acc[mi][nj], ah[mi], bl[nj]);
                }
        }
        __syncthreads();
    }

    // epilogue: bn2 fold, write g_h
#pragma unroll
    for (int mi = 0; mi < 4; mi++) {
        const int m = m0 + warpM * 64 + mi * 16 + (lane >> 2);
#pragma unroll
        for (int nj = 0; nj < 5; nj++) {
            const int n = n0 + warpN * 40 + nj * 8 + (lane & 3) * 2;
            const float2 sc = *(const float2*)&g_scale2[n];
            const float2 sh = *(const float2*)&g_shift2[n];
            float2 v0 = make_float2(acc[mi][nj][0] * sc.x + sh.x,
                                    acc[mi][nj][1] * sc.y + sh.y);
            float2 v1 = make_float2(acc[mi][nj][2] * sc.x + sh.x,
                                    acc[mi][nj][3] * sc.y + sh.y);
            *(float2*)&g_h[(size_t)m * W_IN + n] = v0;
            *(float2*)&g_h[(size_t)(m + 8) * W_IN + n] = v1;
        }
    }
}

// ---------------- final: out[b] = tanh(dot(h[b], fc2_w) + fc2_b) + bias ------
__global__ __launch_bounds__(256) void final_kernel(
    const float* __restrict__ fc2_w, const float* __restrict__ fc2_b,
    const float* __restrict__ bias, float* __restrict__ out)
{
    const int gw = (blockIdx.x * 256 + threadIdx.x) >> 5;
    const int lane = threadIdx.x & 31;
    if (gw >= BATCH) return;
    const float* hrow = g_h + (size_t)gw * W_IN;
    float acc = 0.f;
#pragma unroll
    for (int i = 0; i < 13; i++) {
        int t = lane + i * 32;
        if (t < W_IN) acc += hrow[t] * fc2_w[t];
    }
#pragma unroll
    for (int s = 16; s > 0; s >>= 1) acc += __shfl_xor_sync(0xffffffffu, acc, s);
    if (lane == 0) out[gw] = tanhf(acc + fc2_b[0]) + bias[0];
}

// -----------------------------------------------------------------------------
extern "C" void kernel_launch(void* const* d_in, const int* in_sizes, int n_in,
                              void* d_out, int out_size)
{
    const int*   e1_idx  = (const int*)d_in[0];
    const int*   r_idx   = (const int*)d_in[1];
    const int*   e2_idx  = (const int*)d_in[2];
    const float* E_table = (const float*)d_in[3];
    const float* R_table = (const float*)d_in[4];
    const float* bn0_g   = (const float*)d_in[5];
    const float* bn0_b   = (const float*)d_in[6];
    const float* bn0_m   = (const float*)d_in[7];
    const float* bn0_v   = (const float*)d_in[8];
    const float* fc1_w   = (const float*)d_in[9];
    const float* fc1_b   = (const float*)d_in[10];
    const float* bn1_g   = (const float*)d_in[11];
    const float* bn1_b   = (const float*)d_in[12];
    const float* bn1_m   = (const float*)d_in[13];
    const float* bn1_v   = (const float*)d_in[14];
    const float* fc_w    = (const float*)d_in[15];
    const float* fc_b    = (const float*)d_in[16];
    const float* bn2_g   = (const float*)d_in[17];
    const float* bn2_b   = (const float*)d_in[18];
    const float* bn2_m   = (const float*)d_in[19];
    const float* bn2_v   = (const float*)d_in[20];
    const float* fc2_w   = (const float*)d_in[21];
    const float* fc2_b   = (const float*)d_in[22];
    const float* bias    = (const float*)d_in[23];

    cudaFuncSetAttribute(gemm2_kernel,
                         cudaFuncAttributeMaxDynamicSharedMemorySize, SMEM2);

    setup_kernel<<<1, 512>>>(bn0_g, bn0_b, bn0_m, bn0_v, fc1_b,
                             bn1_g, bn1_b, bn1_m, bn1_v,
                             fc_b, bn2_g, bn2_b, bn2_m, bn2_v);

    splitw_kernel<<<4900, 256>>>(fc_w);

    gemm1_kernel<<<dim3(BATCH / 64, (FC1_LEN + 63) / 64), 128>>>(
        R_table, r_idx, fc1_w, FC1_LEN, D1);

    conv_kernel<<<BATCH, 256>>>(e1_idx, e2_idx, E_table);

    gemm2_kernel<<<dim3(BATCH / BM, W_IN / BN), 128, SMEM2>>>();

    final_kernel<<<(BATCH * 32 + 255) / 256, 256>>>(fc2_w, fc2_b, bias, (float*)d_out);
}

// round 5
// speedup vs baseline: 2.7056x; 1.1312x over previous
#include <cuda_runtime.h>
#include <cuda_bf16.h>
#include <cstdint>
#include <math.h>

#define BATCH 4096
#define D1 200
#define W_IN 400
#define FW 9
#define OC 32
#define W_OUT 392
#define FC_LEN 12544
#define FC1_LEN 288
#define EPSBN 1e-5f

// GEMM2 tiling: CTA 64x80, BK=32, 4-stage cp.async, 128 threads (2x2 warps)
#define BM 64
#define BN 80
#define BK 32
#define NKT (FC_LEN / BK)       // 392
#define ROWB 80                  // smem row stride bytes (32 bf16 + 16B pad)
#define OFF_AL 5120              // 64*80
#define OFF_BH 10240
#define OFF_BL 16640             // +80*80
#define STG 23040                // stage size
#define NSTAGE 4
#define SMEM2 (NSTAGE * STG)     // 92160

// ---------------- device-global scratch (no allocation allowed) --------------
__device__ __align__(16) __nv_bfloat16 g_ah[(size_t)BATCH * FC_LEN];
__device__ __align__(16) __nv_bfloat16 g_al[(size_t)BATCH * FC_LEN];
__device__ __align__(16) __nv_bfloat16 g_bh[(size_t)W_IN * FC_LEN];
__device__ __align__(16) __nv_bfloat16 g_bl[(size_t)W_IN * FC_LEN];
__device__ float g_h[(size_t)BATCH * W_IN];
__device__ float g_ks[BATCH * FC1_LEN];
__device__ float g_scale1[FC1_LEN];
__device__ float g_shift1[FC1_LEN];
__device__ float g_scale2[W_IN];
__device__ float g_shift2[W_IN];
__device__ float g_c1[OC];
__device__ float g_x0[2];

// ---------------- PTX helpers ------------------------------------------------
__device__ __forceinline__ uint32_t smem_u32(const void* p) {
    uint32_t a;
    asm("{ .reg .u64 t; cvta.to.shared.u64 t, %1; cvt.u32.u64 %0, t; }"
        : "=r"(a) : "l"(p));
    return a;
}
__device__ __forceinline__ void cp16(uint32_t sa, const void* ga) {
    asm volatile("cp.async.cg.shared.global [%0], [%1], 16;" :: "r"(sa), "l"(ga));
}
#define CP_COMMIT() asm volatile("cp.async.commit_group;" ::: "memory")
#define CP_WAIT2()  asm volatile("cp.async.wait_group 2;" ::: "memory")

#define LDSM4(r, addr) \
    asm volatile("ldmatrix.sync.aligned.m8n8.x4.shared.b16 {%0,%1,%2,%3}, [%4];" \
                 : "=r"((r)[0]), "=r"((r)[1]), "=r"((r)[2]), "=r"((r)[3]) : "r"(addr))
#define LDSM2(r, addr) \
    asm volatile("ldmatrix.sync.aligned.m8n8.x2.shared.b16 {%0,%1}, [%2];" \
                 : "=r"((r)[0]), "=r"((r)[1]) : "r"(addr))

#define MMA_BF16(c, a, b) \
    asm volatile("mma.sync.aligned.m16n8k16.row.col.f32.bf16.bf16.f32 " \
                 "{%0,%1,%2,%3},{%4,%5,%6,%7},{%8,%9},{%0,%1,%2,%3};" \
                 : "+f"((c)[0]), "+f"((c)[1]), "+f"((c)[2]), "+f"((c)[3]) \
                 : "r"((a)[0]), "r"((a)[1]), "r"((a)[2]), "r"((a)[3]), \
                   "r"((b)[0]), "r"((b)[1]))

// ---------------- setup: fold batchnorms ------------------------------------
__global__ void setup_kernel(
    const float* __restrict__ bn0_g, const float* __restrict__ bn0_b,
    const float* __restrict__ bn0_m, const float* __restrict__ bn0_v,
    const float* __restrict__ fc1_b,
    const float* __restrict__ bn1_g, const float* __restrict__ bn1_b,
    const float* __restrict__ bn1_m, const float* __restrict__ bn1_v,
    const float* __restrict__ fc_b,
    const float* __restrict__ bn2_g, const float* __restrict__ bn2_b,
    const float* __restrict__ bn2_m, const float* __restrict__ bn2_v)
{
    int t = threadIdx.x;
    if (t < FC1_LEN) {
        int o = t / FW;
        float inv1 = bn1_g[o] * rsqrtf(bn1_v[o] + EPSBN);
        g_scale1[t] = inv1;
        g_shift1[t] = fc1_b[t] * inv1;
    }
    if (t < W_IN) {
        float s2 = bn2_g[t] * rsqrtf(bn2_v[t] + EPSBN);
        g_scale2[t] = s2;
        g_shift2[t] = (fc_b[t] - bn2_m[t]) * s2 + bn2_b[t];
    }
    if (t < OC) {
        float inv1 = bn1_g[t] * rsqrtf(bn1_v[t] + EPSBN);
        g_c1[t] = bn1_b[t] - bn1_m[t] * inv1;
    }
    if (t == 0) {
        float s0 = bn0_g[0] * rsqrtf(bn0_v[0] + EPSBN);
        g_x0[0] = s0;
        g_x0[1] = bn0_b[0] - bn0_m[0] * s0;
    }
}

// ---------------- split fc_w into bf16 hi/lo --------------------------------
__global__ __launch_bounds__(256) void splitw_kernel(const float* __restrict__ w)
{
    int i = blockIdx.x * 256 + threadIdx.x;
#pragma unroll
    for (int u = 0; u < 4; u++) {
        size_t idx = (size_t)i + (size_t)u * 1254400;
        float v = w[idx];
        __nv_bfloat16 h = __float2bfloat16(v);
        g_bh[idx] = h;
        g_bl[idx] = __float2bfloat16(v - __bfloat162float(h));
    }
}

// ---------------- GEMM1 (fp32, small): ks = gather(R) @ fc1_w^T --------------
__device__ __forceinline__ float4 ld4p(const float* p, bool v)
{
    if (v) return *(const float4*)p;
    return make_float4(0.f, 0.f, 0.f, 0.f);
}

__global__ __launch_bounds__(128) void gemm1_kernel(
    const float* __restrict__ A, const int* __restrict__ ridx,
    const float* __restrict__ B, int N, int K)
{
    __shared__ float As[16][68];
    __shared__ float Bs[16][68];

    const int tid = threadIdx.x;
    const int m0 = blockIdx.x * 64;
    const int n0 = blockIdx.y * 64;
    const int ldRow = tid >> 2;
    const int ldK = (tid & 3) << 2;

    const int ar0 = m0 + ldRow, ar1 = ar0 + 32;
    const float* ap0 = A + (size_t)ridx[ar0] * K;
    const float* ap1 = A + (size_t)ridx[ar1] * K;
    const int br0 = n0 + ldRow, br1 = br0 + 32;
    const bool bv0 = br0 < N, bv1 = br1 < N;
    const float* bp0 = B + (size_t)(bv0 ? br0 : 0) * K;
    const float* bp1 = B + (size_t)(bv1 ? br1 : 0) * K;

    const int tmi = (tid & 7) << 3;
    const int tni = (tid >> 3) << 2;

    float acc[8][4];
#pragma unroll
    for (int i = 0; i < 8; i++)
#pragma unroll
        for (int j = 0; j < 4; j++) acc[i][j] = 0.f;

    const int nk = (K + 15) >> 4;
    float4 ra0, ra1, rb0, rb1;
    {
        bool kv = ldK < K;
        ra0 = ld4p(ap0 + ldK, kv); ra1 = ld4p(ap1 + ldK, kv);
        rb0 = ld4p(bp0 + ldK, kv && bv0); rb1 = ld4p(bp1 + ldK, kv && bv1);
    }
    for (int kt = 0; kt < nk; kt++) {
        As[ldK + 0][ldRow] = ra0.x; As[ldK + 1][ldRow] = ra0.y;
        As[ldK + 2][ldRow] = ra0.z; As[ldK + 3][ldRow] = ra0.w;
        As[ldK + 0][ldRow + 32] = ra1.x; As[ldK + 1][ldRow + 32] = ra1.y;
        As[ldK + 2][ldRow + 32] = ra1.z; As[ldK + 3][ldRow + 32] = ra1.w;
        Bs[ldK + 0][ldRow] = rb0.x; Bs[ldK + 1][ldRow] = rb0.y;
        Bs[ldK + 2][ldRow] = rb0.z; Bs[ldK + 3][ldRow] = rb0.w;
        Bs[ldK + 0][ldRow + 32] = rb1.x; Bs[ldK + 1][ldRow + 32] = rb1.y;
        Bs[ldK + 2][ldRow + 32] = rb1.z; Bs[ldK + 3][ldRow + 32] = rb1.w;
        __syncthreads();
        if (kt + 1 < nk) {
            int kk = ((kt + 1) << 4) + ldK;
            bool kv = kk < K;
            ra0 = ld4p(ap0 + kk, kv); ra1 = ld4p(ap1 + kk, kv);
            rb0 = ld4p(bp0 + kk, kv && bv0); rb1 = ld4p(bp1 + kk, kv && bv1);
        }
#pragma unroll
        for (int k = 0; k < 16; k++) {
            float4 a0 = *(const float4*)&As[k][tmi];
            float4 a1 = *(const float4*)&As[k][tmi + 4];
            float4 bb = *(const float4*)&Bs[k][tni];
            float av[8] = {a0.x, a0.y, a0.z, a0.w, a1.x, a1.y, a1.z, a1.w};
            float bv[4] = {bb.x, bb.y, bb.z, bb.w};
#pragma unroll
            for (int i = 0; i < 8; i++)
#pragma unroll
                for (int j = 0; j < 4; j++) acc[i][j] += av[i] * bv[j];
        }
        __syncthreads();
    }
#pragma unroll
    for (int j = 0; j < 4; j++) {
        int col = n0 + tni + j;
        if (col < N) {
            float sc = g_scale1[col], sh = g_shift1[col];
#pragma unroll
            for (int i = 0; i < 8; i++)
                g_ks[(size_t)(m0 + tmi + i) * N + col] = acc[i][j] * sc + sh;
        }
    }
}

// ---------------- conv: bf16 hi/lo of bn1(conv(bn0(x), k)), low-reg ----------
// 128 threads / CTA, one CTA per example. Warp handles one o at a time
// (8 o's per warp over the oi loop); lanes write bf16x2 pairs -> coalesced.
__global__ __launch_bounds__(128) void conv_kernel(
    const int* __restrict__ e1_idx, const int* __restrict__ e2_idx,
    const float* __restrict__ E_table)
{
    __shared__ float sx[W_IN];
    __shared__ float sks[FC1_LEN];
    __shared__ float sc1[OC];

    const int b = blockIdx.x;
    const int tid = threadIdx.x;
    const float s0 = g_x0[0], o0 = g_x0[1];
    const int e1 = e1_idx[b], e2 = e2_idx[b];

    for (int t = tid; t < W_IN; t += 128) {
        float e = (t < D1) ? E_table[(size_t)e1 * D1 + t]
                           : E_table[(size_t)e2 * D1 + (t - D1)];
        sx[t] = e * s0 + o0;
    }
    for (int t = tid; t < FC1_LEN; t += 128) sks[t] = g_ks[(size_t)b * FC1_LEN + t];
    if (tid < OC) sc1[tid] = g_c1[tid];
    __syncthreads();

    const int warp = tid >> 5, lane = tid & 31;

    for (int oi = 0; oi < 8; oi++) {
        const int o = oi * 4 + warp;
        float kf[FW];
#pragma unroll
        for (int j = 0; j < FW; j++) kf[j] = sks[o * FW + j];
        const float c = sc1[o];
        const size_t base = (size_t)b * FC_LEN + o * W_OUT;
        __nv_bfloat162* dh = (__nv_bfloat162*)(g_ah + base);
        __nv_bfloat162* dl = (__nv_bfloat162*)(g_al + base);
#pragma unroll
        for (int it = 0; it < 7; it++) {
            int p = it * 32 + lane;          // pair index, 196 pairs
            if (p < 196) {
                int w = p * 2;
                float a0 = c, a1 = c;
#pragma unroll
                for (int j = 0; j < FW; j++) {
                    a0 += sx[w + j] * kf[j];
                    a1 += sx[w + 1 + j] * kf[j];
                }
                __nv_bfloat16 h0 = __float2bfloat16(a0);
                __nv_bfloat16 h1 = __float2bfloat16(a1);
                __nv_bfloat16 l0 = __float2bfloat16(a0 - __bfloat162float(h0));
                __nv_bfloat16 l1 = __float2bfloat16(a1 - __bfloat162float(h1));
                dh[p] = __nv_bfloat162{h0, h1};
                dl[p] = __nv_bfloat162{l0, l1};
            }
        }
    }
}

// ---------------- GEMM2: mma.sync bf16 3-term split, 4-stage pipeline --------
// grid (5, 64): n fast (same-m CTAs share A in L2). 128 threads, warp 32x40.
__global__ __launch_bounds__(128, 2) void gemm2_kernel()
{
    extern __shared__ char smem[];
    const int tid = threadIdx.x;
    const int wid = tid >> 5, lane = tid & 31;
    const int warpM = wid >> 1, warpN = wid & 1;
    const int n0 = blockIdx.x * BN;
    const int m0 = blockIdx.y * BM;
    const uint32_t sb = smem_u32(smem);

    float acc[2][5][4];
#pragma unroll
    for (int mi = 0; mi < 2; mi++)
#pragma unroll
        for (int nj = 0; nj < 5; nj++)
#pragma unroll
            for (int q = 0; q < 4; q++) acc[mi][nj][q] = 0.f;

    auto issue = [&](int kt) {
        const int kb = kt * BK;
        const uint32_t s = sb + (kt & (NSTAGE - 1)) * STG;
#pragma unroll
        for (int i = 0; i < 2; i++) {
            int idx = tid + i * 128;          // 0..255
            int r = idx >> 2, c = idx & 3;
            size_t go = (size_t)(m0 + r) * FC_LEN + kb + c * 8;
            uint32_t so = r * ROWB + c * 16;
            cp16(s + so, g_ah + go);
            cp16(s + OFF_AL + so, g_al + go);
        }
#pragma unroll
        for (int i = 0; i < 3; i++) {
            int idx = tid + i * 128;          // need < 320
            if (idx < 320) {
                int r = idx >> 2, c = idx & 3;
                size_t go = (size_t)(n0 + r) * FC_LEN + kb + c * 8;
                uint32_t so = r * ROWB + c * 16;
                cp16(s + OFF_BH + so, g_bh + go);
                cp16(s + OFF_BL + so, g_bl + go);
            }
        }
        CP_COMMIT();
    };

    issue(0); issue(1); issue(2);

    const uint32_t aOff = (warpM * 32 + (lane & 15)) * ROWB + (((uint32_t)lane >> 4) << 4);
    const int l16 = lane & 15;
    const uint32_t bOff = (warpN * 40 + (l16 & 7)) * ROWB + (((uint32_t)l16 >> 3) << 4);

    for (int kt = 0; kt < NKT; kt++) {
        CP_WAIT2();
        __syncthreads();
        if (kt + 3 < NKT) issue(kt + 3);
        else CP_COMMIT();

        const uint32_t sA = sb + (kt & (NSTAGE - 1)) * STG;
#pragma unroll
        for (int kk = 0; kk < 2; kk++) {
            const uint32_t koff = kk * 32;
            uint32_t ah[2][4], al[2][4], bh[5][2], bl[5][2];
#pragma unroll
            for (int mi = 0; mi < 2; mi++) {
                LDSM4(ah[mi], sA + aOff + mi * 16 * ROWB + koff);
                LDSM4(al[mi], sA + OFF_AL + aOff + mi * 16 * ROWB + koff);
            }
#pragma unroll
            for (int nj = 0; nj < 5; nj++) {
                LDSM2(bh[nj], sA + OFF_BH + bOff + nj * 8 * ROWB + koff);
                LDSM2(bl[nj], sA + OFF_BL + bOff + nj * 8 * ROWB + koff);
            }
#pragma unroll
            for (int mi = 0; mi < 2; mi++)
#pragma unroll
                for (int nj = 0; nj < 5; nj++) {
                    MMA_BF16(acc[mi][nj], ah[mi], bh[nj]);
                    MMA_BF16(acc[mi][nj], al[mi], bh[nj]);
                    MMA_BF16(acc[mi][nj], ah[mi], bl[nj]);
                }
        }
    }

    // epilogue: bn2 fold, write g_h
#pragma unroll
    for (int mi = 0; mi < 2; mi++) {
        const int m = m0 + warpM * 32 + mi * 16 + (lane >> 2);
#pragma unroll
        for (int nj = 0; nj < 5; nj++) {
            const int n = n0 + warpN * 40 + nj * 8 + (lane & 3) * 2;
            const float2 sc = *(const float2*)&g_scale2[n];
            const float2 sh = *(const float2*)&g_shift2[n];
            float2 v0 = make_float2(acc[mi][nj][0] * sc.x + sh.x,
                                    acc[mi][nj][1] * sc.y + sh.y);
            float2 v1 = make_float2(acc[mi][nj][2] * sc.x + sh.x,
                                    acc[mi][nj][3] * sc.y + sh.y);
            *(float2*)&g_h[(size_t)m * W_IN + n] = v0;
            *(float2*)&g_h[(size_t)(m + 8) * W_IN + n] = v1;
        }
    }
}

// ---------------- final: out[b] = tanh(dot(h[b], fc2_w) + fc2_b) + bias ------
__global__ __launch_bounds__(256) void final_kernel(
    const float* __restrict__ fc2_w, const float* __restrict__ fc2_b,
    const float* __restrict__ bias, float* __restrict__ out)
{
    const int gw = (blockIdx.x * 256 + threadIdx.x) >> 5;
    const int lane = threadIdx.x & 31;
    if (gw >= BATCH) return;
    const float* hrow = g_h + (size_t)gw * W_IN;
    float acc = 0.f;
#pragma unroll
    for (int i = 0; i < 13; i++) {
        int t = lane + i * 32;
        if (t < W_IN) acc += hrow[t] * fc2_w[t];
    }
#pragma unroll
    for (int s = 16; s > 0; s >>= 1) acc += __shfl_xor_sync(0xffffffffu, acc, s);
    if (lane == 0) out[gw] = tanhf(acc + fc2_b[0]) + bias[0];
}

// -----------------------------------------------------------------------------
extern "C" void kernel_launch(void* const* d_in, const int* in_sizes, int n_in,
                              void* d_out, int out_size)
{
    const int*   e1_idx  = (const int*)d_in[0];
    const int*   r_idx   = (const int*)d_in[1];
    const int*   e2_idx  = (const int*)d_in[2];
    const float* E_table = (const float*)d_in[3];
    const float* R_table = (const float*)d_in[4];
    const float* bn0_g   = (const float*)d_in[5];
    const float* bn0_b   = (const float*)d_in[6];
    const float* bn0_m   = (const float*)d_in[7];
    const float* bn0_v   = (const float*)d_in[8];
    const float* fc1_w   = (const float*)d_in[9];
    const float* fc1_b   = (const float*)d_in[10];
    const float* bn1_g   = (const float*)d_in[11];
    const float* bn1_b   = (const float*)d_in[12];
    const float* bn1_m   = (const float*)d_in[13];
    const float* bn1_v   = (const float*)d_in[14];
    const float* fc_w    = (const float*)d_in[15];
    const float* fc_b    = (const float*)d_in[16];
    const float* bn2_g   = (const float*)d_in[17];
    const float* bn2_b   = (const float*)d_in[18];
    const float* bn2_m   = (const float*)d_in[19];
    const float* bn2_v   = (const float*)d_in[20];
    const float* fc2_w   = (const float*)d_in[21];
    const float* fc2_b   = (const float*)d_in[22];
    const float* bias    = (const float*)d_in[23];

    cudaFuncSetAttribute(gemm2_kernel,
                         cudaFuncAttributeMaxDynamicSharedMemorySize, SMEM2);

    setup_kernel<<<1, 512>>>(bn0_g, bn0_b, bn0_m, bn0_v, fc1_b,
                             bn1_g, bn1_b, bn1_m, bn1_v,
                             fc_b, bn2_g, bn2_b, bn2_m, bn2_v);

    splitw_kernel<<<4900, 256>>>(fc_w);

    gemm1_kernel<<<dim3(BATCH / 64, (FC1_LEN + 63) / 64), 128>>>(
        R_table, r_idx, fc1_w, FC1_LEN, D1);

    conv_kernel<<<BATCH, 128>>>(e1_idx, e2_idx, E_table);

    gemm2_kernel<<<dim3(W_IN / BN, BATCH / BM), 128, SMEM2>>>();

    final_kernel<<<(BATCH * 32 + 255) / 256, 256>>>(fc2_w, fc2_b, bias, (float*)d_out);
}